// round 14
// baseline (speedup 1.0000x reference)
#include <cuda_runtime.h>
#include <cuda_fp16.h>
#include <math.h>
#include <stdint.h>

#define T      4096
#define DIM    1024
#define E      8
#define HDIM   2048
#define NSLOT  (T * 2)
#define EPS    1e-5f

// ---------------- device scratch (static, allocation-free) ----------------
__device__ float g_y[(size_t)NSLOT * DIM];
__device__ __half g_xf[(size_t)T * DIM];
__device__ __half g_act[(size_t)NSLOT * HDIM];     // GEMM1 out (fp16), LN+GELU in-place
__device__ __half g_w1f[(size_t)E * DIM * HDIM];   // [E][K=1024][N=2048]
__device__ __half g_w2f[(size_t)E * HDIM * DIM];   // [E][K=2048][N=1024]
__device__ int   g_cnt[E];
__device__ int   g_cur[E];
__device__ int   g_off[E + 1];
__device__ int   g_topi[NSLOT];
__device__ float g_topw[NSLOT];
__device__ int   g_slot_token[NSLOT];
__device__ int   g_slot_e[NSLOT];
__device__ float g_slot_w[NSLOT];
__device__ int   g_tok_slot[NSLOT];

// ---------------- PTX helpers ----------------
__device__ __forceinline__ uint32_t s2u(const void* p) {
    uint32_t a;
    asm("{ .reg .u64 t; cvta.to.shared.u64 t, %1; cvt.u32.u64 %0, t; }" : "=r"(a) : "l"(p));
    return a;
}

#define CP_ASYNC(sa, ga) \
    asm volatile("cp.async.cg.shared.global [%0], [%1], 16;" :: "r"(sa), "l"(ga))
#define CP_COMMIT() asm volatile("cp.async.commit_group;" ::: "memory")
#define CP_WAIT4()  asm volatile("cp.async.wait_group 4;" ::: "memory")

#define LDSM4(r, addr) \
    asm volatile("ldmatrix.sync.aligned.m8n8.x4.shared.b16 {%0,%1,%2,%3}, [%4];" \
        : "=r"((r)[0]), "=r"((r)[1]), "=r"((r)[2]), "=r"((r)[3]) : "r"(addr))
#define LDSM4T(r, addr) \
    asm volatile("ldmatrix.sync.aligned.m8n8.x4.trans.shared.b16 {%0,%1,%2,%3}, [%4];" \
        : "=r"((r)[0]), "=r"((r)[1]), "=r"((r)[2]), "=r"((r)[3]) : "r"(addr))

#define MMA(acc, a, b) \
    asm volatile("mma.sync.aligned.m16n8k16.row.col.f32.f16.f16.f32 " \
        "{%0,%1,%2,%3}, {%4,%5,%6,%7}, {%8,%9}, {%0,%1,%2,%3};" \
        : "+f"((acc)[0]), "+f"((acc)[1]), "+f"((acc)[2]), "+f"((acc)[3]) \
        : "r"((a)[0]), "r"((a)[1]), "r"((a)[2]), "r"((a)[3]), "r"((b)[0]), "r"((b)[1]))

// ---------------- prep: init counters + convert w1/w2 to fp16 --------------
#define NW4  ((size_t)E * DIM * HDIM / 4)
#define NPREP (2 * NW4)

__global__ void prep_kernel(const float* __restrict__ w1,
                            const float* __restrict__ w2) {
    size_t i = (size_t)blockIdx.x * blockDim.x + threadIdx.x;
    if (i < E) { g_cnt[i] = 0; g_cur[i] = 0; }
    if (i >= NPREP) return;
    const float* src;
    __half2* dst;
    size_t j;
    if (i < NW4) { src = w1; dst = (__half2*)g_w1f; j = i; }
    else         { src = w2; dst = (__half2*)g_w2f; j = i - NW4; }
    float4 v = ((const float4*)src)[j];
    dst[2 * j]     = __floats2half2_rn(v.x, v.y);
    dst[2 * j + 1] = __floats2half2_rn(v.z, v.w);
}

// ---------------- gating: one warp per token (+ fused x->fp16) -------------
__global__ void gate_kernel(const float* __restrict__ x, const float* __restrict__ gw) {
    int warp = (blockIdx.x * blockDim.x + threadIdx.x) >> 5;
    int lane = threadIdx.x & 31;
    if (warp >= T) return;
    const float* xr = x + (size_t)warp * DIM;
    __half2* xo = (__half2*)(g_xf + (size_t)warp * DIM);
    float acc[E];
#pragma unroll
    for (int e = 0; e < E; e++) acc[e] = 0.f;
    for (int d2 = lane; d2 < DIM / 2; d2 += 32) {
        float2 xv = ((const float2*)xr)[d2];
        xo[d2] = __floats2half2_rn(xv.x, xv.y);       // fused fp16 emit
        const float* g0 = gw + (2 * d2) * E;
#pragma unroll
        for (int e = 0; e < E; e++) acc[e] += xv.x * g0[e] + xv.y * g0[E + e];
    }
#pragma unroll
    for (int e = 0; e < E; e++)
#pragma unroll
        for (int o = 16; o; o >>= 1) acc[e] += __shfl_xor_sync(0xffffffffu, acc[e], o);
    if (lane == 0) {
        int i1 = 0; float l1 = acc[0];
#pragma unroll
        for (int e = 1; e < E; e++) if (acc[e] > l1) { l1 = acc[e]; i1 = e; }
        int i2 = -1; float l2 = -INFINITY;
#pragma unroll
        for (int e = 0; e < E; e++) if (e != i1 && acc[e] > l2) { l2 = acc[e]; i2 = e; }
        float w1 = 1.f / (1.f + expf(l2 - l1));   // exact normalized top-2 softmax
        g_topi[2 * warp] = i1;  g_topi[2 * warp + 1] = i2;
        g_topw[2 * warp] = w1;  g_topw[2 * warp + 1] = 1.f - w1;
        atomicAdd(&g_cnt[i1], 1);
        atomicAdd(&g_cnt[i2], 1);
    }
}

// ---------------- scatter (with local prefix scan of 8 counts) -------------
__global__ void scatter_kernel() {
    __shared__ int soff[E + 1];
    if (threadIdx.x == 0) {
        int acc = 0;
#pragma unroll
        for (int e = 0; e < E; e++) { soff[e] = acc; acc += g_cnt[e]; }
        soff[E] = acc;
        if (blockIdx.x == 0) {
#pragma unroll
            for (int e = 0; e <= E; e++) g_off[e] = soff[e];
        }
    }
    __syncthreads();
    int t = blockIdx.x * blockDim.x + threadIdx.x;
    if (t >= T) return;
#pragma unroll
    for (int k = 0; k < 2; k++) {
        int e = g_topi[2 * t + k];
        int p = soff[e] + atomicAdd(&g_cur[e], 1);
        g_slot_token[p] = t;
        g_slot_e[p]     = e;
        g_slot_w[p]     = g_topw[2 * t + k];
        g_tok_slot[2 * t + k] = p;
    }
}

// ---------------- mma.sync grouped GEMM (fp16, 16 warps) -------------------
// Block tile 128(M) x 256(N), K-chunk 32, 6 stages, 16 warps (4x4),
// warp tile 32x64 -> 4 warps/SMSP for latency hiding.
// A smem: [128][32] fp16, row stride 80B (conflict-free ldmatrix)
// B smem: [32][256] fp16, row stride 528B (conflict-free ldmatrix.trans)
#define A_STRIDE 80
#define B_STRIDE 528
#define B_OFF    (128 * A_STRIDE)            // 10240
#define STAGE_SZ (B_OFF + 32 * B_STRIDE)     // 27136
#define NSTAGE   6
#define MM_SMEM  (1024 + NSTAGE * STAGE_SZ)  // 163840
#define NTHR     512

template <int NT, int KD, int MODE>
__global__ void __launch_bounds__(NTHR, 1) mma_gemm(const float* __restrict__ bias) {
    const int e    = blockIdx.z;
    const int base = g_off[e];
    const int cnt  = g_off[e + 1] - base;
    const int row0 = blockIdx.y * 128;
    if (row0 >= cnt) return;
    const int n0 = blockIdx.x * 256;

    extern __shared__ __align__(128) char smem[];
    const uint32_t sb = s2u(smem);
    int* rowidx = (int*)smem;
    const int tid = threadIdx.x, wid = tid >> 5, lane = tid & 31;

    const __half* __restrict__ Asrc = (MODE == 0) ? g_xf : g_act;
    const __half* __restrict__ Bsrc =
        ((MODE == 0) ? g_w1f : g_w2f) + (size_t)e * KD * NT + n0;

    if (tid < 128) {
        int r = row0 + tid; if (r > cnt - 1) r = cnt - 1;
        rowidx[tid] = (MODE == 0) ? g_slot_token[base + r] : (base + r);
    }
    __syncthreads();

    // per-thread cp.async coordinates (512 threads)
    const int ar = tid >> 2, ac = tid & 3;       // A: 1x16B per thread
    const int br = tid >> 4, bc = tid & 15;      // B: 2x16B per thread

    auto issue = [&](int c) {
        const int k0 = c * 32;
        const uint32_t s = sb + 1024 + (c % NSTAGE) * STAGE_SZ;
        {
            size_t go = (size_t)rowidx[ar] * KD + k0 + ac * 8;
            CP_ASYNC(s + ar * A_STRIDE + ac * 16, Asrc + go);
        }
        {
            size_t go = (size_t)(k0 + br) * NT + bc * 8;
            uint32_t so = s + B_OFF + br * B_STRIDE + bc * 16;
            CP_ASYNC(so, Bsrc + go);
            CP_ASYNC(so + 256, Bsrc + go + 128);
        }
        CP_COMMIT();
    };

    float acc[2][8][4];
#pragma unroll
    for (int i = 0; i < 2; i++)
#pragma unroll
        for (int j = 0; j < 8; j++)
#pragma unroll
            for (int q = 0; q < 4; q++) acc[i][j][q] = 0.f;

    const int warp_m = wid >> 2, warp_n = wid & 3;   // 4x4 warps, tile 32x64
    const int mat = lane >> 3, rin = lane & 7;
    const uint32_t aOffBase = (uint32_t)((warp_m * 32 + rin + (mat & 1) * 8) * A_STRIDE
                                         + (mat >> 1) * 16);
    const uint32_t bOffBase = (uint32_t)(B_OFF + ((mat & 1) * 8 + rin) * B_STRIDE
                                         + (warp_n * 64 + (mat >> 1) * 8) * 2);

    constexpr int NCH = KD / 32;
    issue(0); issue(1); issue(2); issue(3); issue(4);

    for (int c = 0; c < NCH; c++) {
        CP_WAIT4();
        __syncthreads();
        const uint32_t s = sb + 1024 + (c % NSTAGE) * STAGE_SZ;
#pragma unroll
        for (int ks = 0; ks < 2; ks++) {
            uint32_t ah[2][4];
            uint32_t aAddr = s + aOffBase + ks * 32;
#pragma unroll
            for (int i = 0; i < 2; i++) LDSM4(ah[i], aAddr + i * 16 * A_STRIDE);
#pragma unroll
            for (int jh = 0; jh < 2; jh++) {
                uint32_t bh[4][2];
                uint32_t bAddr = s + bOffBase + ks * 16 * B_STRIDE + jh * 64;
                LDSM4T(&bh[0][0], bAddr);
                LDSM4T(&bh[2][0], bAddr + 32);
#pragma unroll
                for (int i = 0; i < 2; i++)
#pragma unroll
                    for (int j = 0; j < 4; j++) MMA(acc[i][jh * 4 + j], ah[i], bh[j]);
            }
        }
        if (c + 5 < NCH) issue(c + 5);
        else CP_COMMIT();
    }

    // epilogue: warp rows warp_m*32 + i*16 + lane/4 (+8), cols warp_n*64 + j*8
    const float* bp = bias + (size_t)e * NT;
#pragma unroll
    for (int i = 0; i < 2; i++) {
        int r1 = row0 + warp_m * 32 + i * 16 + (lane >> 2);
        int r2 = r1 + 8;
        bool v1 = r1 < cnt, v2 = r2 < cnt;
        float w1g = 1.f, w2g = 1.f;
        if (MODE == 1) {
            if (v1) w1g = g_slot_w[base + r1];
            if (v2) w2g = g_slot_w[base + r2];
        }
#pragma unroll
        for (int j = 0; j < 8; j++) {
            int col = n0 + warp_n * 64 + j * 8 + (lane & 3) * 2;
            float b0 = bp[col], b1 = bp[col + 1];
            if (MODE == 0) {
                if (v1) {
                    *(__half2*)(g_act + (size_t)(base + r1) * NT + col) =
                        __floats2half2_rn(acc[i][j][0] + b0, acc[i][j][1] + b1);
                }
                if (v2) {
                    *(__half2*)(g_act + (size_t)(base + r2) * NT + col) =
                        __floats2half2_rn(acc[i][j][2] + b0, acc[i][j][3] + b1);
                }
            } else {
                if (v1) {
                    float2 o = make_float2((acc[i][j][0] + b0) * w1g,
                                           (acc[i][j][1] + b1) * w1g);
                    *(float2*)(g_y + (size_t)(base + r1) * NT + col) = o;
                }
                if (v2) {
                    float2 o = make_float2((acc[i][j][2] + b0) * w2g,
                                           (acc[i][j][3] + b1) * w2g);
                    *(float2*)(g_y + (size_t)(base + r2) * NT + col) = o;
                }
            }
        }
    }
}

// ---------------- block reduction helper ----------------
__device__ __forceinline__ float2 block_reduce2(float a, float b) {
#pragma unroll
    for (int o = 16; o; o >>= 1) {
        a += __shfl_xor_sync(0xffffffffu, a, o);
        b += __shfl_xor_sync(0xffffffffu, b, o);
    }
    __shared__ float2 sm[8];
    int w = threadIdx.x >> 5, l = threadIdx.x & 31;
    if (l == 0) sm[w] = make_float2(a, b);
    __syncthreads();
    if (w == 0) {
        float2 v = (l < 8) ? sm[l] : make_float2(0.f, 0.f);
#pragma unroll
        for (int o = 4; o; o >>= 1) {
            v.x += __shfl_xor_sync(0xffffffffu, v.x, o);
            v.y += __shfl_xor_sync(0xffffffffu, v.y, o);
        }
        if (l == 0) sm[0] = v;
    }
    __syncthreads();
    return sm[0];
}

// ---------------- LN1 + exact GELU, in-place on fp16 g_act ----------------
__global__ __launch_bounds__(256) void ln_gelu_kernel(
    const float* __restrict__ ln1_g, const float* __restrict__ ln1_b) {
    int s = blockIdx.x;
    int e = g_slot_e[s];
    __half* row = g_act + (size_t)s * HDIM;
    int t = threadIdx.x;

    uint4 raw = ((const uint4*)row)[t];            // 8 halfs per thread
    __half2 h2[4];
    h2[0] = *(__half2*)&raw.x; h2[1] = *(__half2*)&raw.y;
    h2[2] = *(__half2*)&raw.z; h2[3] = *(__half2*)&raw.w;
    float va[8];
#pragma unroll
    for (int i = 0; i < 4; i++) {
        float2 f = __half22float2(h2[i]);
        va[2 * i] = f.x; va[2 * i + 1] = f.y;
    }
    float sum = 0.f, sq = 0.f;
#pragma unroll
    for (int i = 0; i < 8; i++) { sum += va[i]; sq += va[i] * va[i]; }
    float2 r = block_reduce2(sum, sq);
    float mean = r.x * (1.f / HDIM);
    float var  = r.y * (1.f / HDIM) - mean * mean;
    float rstd = rsqrtf(var + EPS);

    const float4 gg0 = ((const float4*)(ln1_g + (size_t)e * HDIM))[2 * t];
    const float4 gg1 = ((const float4*)(ln1_g + (size_t)e * HDIM))[2 * t + 1];
    const float4 bb0 = ((const float4*)(ln1_b + (size_t)e * HDIM))[2 * t];
    const float4 bb1 = ((const float4*)(ln1_b + (size_t)e * HDIM))[2 * t + 1];
    float ga[8] = {gg0.x, gg0.y, gg0.z, gg0.w, gg1.x, gg1.y, gg1.z, gg1.w};
    float ba[8] = {bb0.x, bb0.y, bb0.z, bb0.w, bb1.x, bb1.y, bb1.z, bb1.w};

    float gv[8];
#pragma unroll
    for (int i = 0; i < 8; i++) {
        float u = (va[i] - mean) * rstd * ga[i] + ba[i];
        gv[i] = 0.5f * u * (1.f + erff(u * 0.70710678118654752f));
    }
    uint4 outw;
    *(__half2*)&outw.x = __floats2half2_rn(gv[0], gv[1]);
    *(__half2*)&outw.y = __floats2half2_rn(gv[2], gv[3]);
    *(__half2*)&outw.z = __floats2half2_rn(gv[4], gv[5]);
    *(__half2*)&outw.w = __floats2half2_rn(gv[6], gv[7]);
    ((uint4*)row)[t] = outw;
}

// ---------------- combine: out = LN(x + y0 + y1) ----------------
__global__ __launch_bounds__(256) void combine_kernel(
    const float* __restrict__ x, const float* __restrict__ ln_g,
    const float* __restrict__ ln_b, float* __restrict__ outp) {
    int tkn = blockIdx.x;
    int s0 = g_tok_slot[2 * tkn], s1 = g_tok_slot[2 * tkn + 1];
    int t = threadIdx.x;

    float4 xv = ((const float4*)(x + (size_t)tkn * DIM))[t];
    float4 y0 = ((const float4*)(g_y + (size_t)s0 * DIM))[t];
    float4 y1 = ((const float4*)(g_y + (size_t)s1 * DIM))[t];
    float4 v = make_float4(xv.x + y0.x + y1.x, xv.y + y0.y + y1.y,
                           xv.z + y0.z + y1.z, xv.w + y0.w + y1.w);
    float sum = v.x + v.y + v.z + v.w;
    float sq  = v.x * v.x + v.y * v.y + v.z * v.z + v.w * v.w;
    float2 r = block_reduce2(sum, sq);
    float mean = r.x * (1.f / DIM);
    float var  = r.y * (1.f / DIM) - mean * mean;
    float rstd = rsqrtf(var + EPS);

    float4 gg = ((const float4*)ln_g)[t];
    float4 bb = ((const float4*)ln_b)[t];
    float4 o = make_float4((v.x - mean) * rstd * gg.x + bb.x,
                           (v.y - mean) * rstd * gg.y + bb.y,
                           (v.z - mean) * rstd * gg.z + bb.z,
                           (v.w - mean) * rstd * gg.w + bb.w);
    ((float4*)(outp + (size_t)tkn * DIM))[t] = o;
}

// ---------------- launch ----------------
extern "C" void kernel_launch(void* const* d_in, const int* in_sizes, int n_in,
                              void* d_out, int out_size) {
    const float* x      = (const float*)d_in[0];
    const float* gate_w = (const float*)d_in[1];
    const float* w1     = (const float*)d_in[2];
    const float* b1     = (const float*)d_in[3];
    const float* ln1_g  = (const float*)d_in[4];
    const float* ln1_b  = (const float*)d_in[5];
    const float* w2     = (const float*)d_in[6];
    const float* b2     = (const float*)d_in[7];
    const float* ln_g   = (const float*)d_in[8];
    const float* ln_b   = (const float*)d_in[9];
    float* outp = (float*)d_out;

    cudaFuncSetAttribute(mma_gemm<HDIM, DIM, 0>,
                         cudaFuncAttributeMaxDynamicSharedMemorySize, MM_SMEM);
    cudaFuncSetAttribute(mma_gemm<DIM, HDIM, 1>,
                         cudaFuncAttributeMaxDynamicSharedMemorySize, MM_SMEM);

    // prep: init counters + fp32->fp16 conversion of w1, w2
    prep_kernel<<<(int)((NPREP + 255) / 256), 256>>>(w1, w2);
    // gate: routing + fused x->fp16 conversion
    gate_kernel<<<T / 8, 256>>>(x, gate_w);
    scatter_kernel<<<T / 256, 256>>>();

    // GEMM1: gathered x @ w1 + b1 -> g_act (fp16)
    mma_gemm<HDIM, DIM, 0><<<dim3(HDIM / 256, T / 128, E), NTHR, MM_SMEM>>>(b1);
    ln_gelu_kernel<<<NSLOT, 256>>>(ln1_g, ln1_b);
    // GEMM2: act @ w2 + b2, gate-scaled -> g_y (fp32)
    mma_gemm<DIM, HDIM, 1><<<dim3(DIM / 256, T / 128, E), NTHR, MM_SMEM>>>(b2);
    combine_kernel<<<T, 256>>>(x, ln_g, ln_b, outp);
}

// round 15
// speedup vs baseline: 1.1045x; 1.1045x over previous
#include <cuda_runtime.h>
#include <cuda_fp16.h>
#include <math.h>
#include <stdint.h>

#define T      4096
#define DIM    1024
#define E      8
#define HDIM   2048
#define NSLOT  (T * 2)
#define EPS    1e-5f

// ---------------- device scratch (static, allocation-free) ----------------
__device__ float g_y[(size_t)NSLOT * DIM];
__device__ __half g_xf[(size_t)T * DIM];
__device__ __half g_act[(size_t)NSLOT * HDIM];     // GEMM1 out (fp16), LN+GELU in-place
__device__ __half g_w1f[(size_t)E * DIM * HDIM];   // [E][K=1024][N=2048]
__device__ __half g_w2f[(size_t)E * HDIM * DIM];   // [E][K=2048][N=1024]
__device__ int   g_cnt[E];
__device__ int   g_cur[E];
__device__ int   g_off[E + 1];
__device__ int   g_topi[NSLOT];
__device__ float g_topw[NSLOT];
__device__ int   g_slot_token[NSLOT];
__device__ int   g_slot_e[NSLOT];
__device__ float g_slot_w[NSLOT];
__device__ int   g_tok_slot[NSLOT];

// ---------------- PTX helpers ----------------
__device__ __forceinline__ uint32_t s2u(const void* p) {
    uint32_t a;
    asm("{ .reg .u64 t; cvta.to.shared.u64 t, %1; cvt.u32.u64 %0, t; }" : "=r"(a) : "l"(p));
    return a;
}

#define CP_ASYNC(sa, ga) \
    asm volatile("cp.async.cg.shared.global [%0], [%1], 16;" :: "r"(sa), "l"(ga))
#define CP_COMMIT() asm volatile("cp.async.commit_group;" ::: "memory")
#define CP_WAIT3()  asm volatile("cp.async.wait_group 3;" ::: "memory")

#define LDSM4(r, addr) \
    asm volatile("ldmatrix.sync.aligned.m8n8.x4.shared.b16 {%0,%1,%2,%3}, [%4];" \
        : "=r"((r)[0]), "=r"((r)[1]), "=r"((r)[2]), "=r"((r)[3]) : "r"(addr))
#define LDSM4T(r, addr) \
    asm volatile("ldmatrix.sync.aligned.m8n8.x4.trans.shared.b16 {%0,%1,%2,%3}, [%4];" \
        : "=r"((r)[0]), "=r"((r)[1]), "=r"((r)[2]), "=r"((r)[3]) : "r"(addr))

#define MMA(acc, a, b) \
    asm volatile("mma.sync.aligned.m16n8k16.row.col.f32.f16.f16.f32 " \
        "{%0,%1,%2,%3}, {%4,%5,%6,%7}, {%8,%9}, {%0,%1,%2,%3};" \
        : "+f"((acc)[0]), "+f"((acc)[1]), "+f"((acc)[2]), "+f"((acc)[3]) \
        : "r"((a)[0]), "r"((a)[1]), "r"((a)[2]), "r"((a)[3]), "r"((b)[0]), "r"((b)[1]))

// ---------------- fused prep: init counters + convert x/w1/w2 to fp16 ------
#define NX4  ((size_t)T * DIM / 4)
#define NW4  ((size_t)E * DIM * HDIM / 4)
#define NPREP (NX4 + 2 * NW4)

__global__ void prep_kernel(const float* __restrict__ x,
                            const float* __restrict__ w1,
                            const float* __restrict__ w2) {
    size_t i = (size_t)blockIdx.x * blockDim.x + threadIdx.x;
    if (i < E) { g_cnt[i] = 0; g_cur[i] = 0; }
    if (i >= NPREP) return;
    const float* src;
    __half2* dst;
    size_t j;
    if (i < NX4)            { src = x;  dst = (__half2*)g_xf;  j = i; }
    else if (i < NX4 + NW4) { src = w1; dst = (__half2*)g_w1f; j = i - NX4; }
    else                    { src = w2; dst = (__half2*)g_w2f; j = i - NX4 - NW4; }
    float4 v = ((const float4*)src)[j];
    dst[2 * j]     = __floats2half2_rn(v.x, v.y);
    dst[2 * j + 1] = __floats2half2_rn(v.z, v.w);
}

// ---------------- gating: one warp per token ----------------
__global__ void gate_kernel(const float* __restrict__ x, const float* __restrict__ gw) {
    int warp = (blockIdx.x * blockDim.x + threadIdx.x) >> 5;
    int lane = threadIdx.x & 31;
    if (warp >= T) return;
    const float* xr = x + (size_t)warp * DIM;
    float acc[E];
#pragma unroll
    for (int e = 0; e < E; e++) acc[e] = 0.f;
    for (int d = lane; d < DIM; d += 32) {
        float xv = xr[d];
        const float* g = gw + d * E;
#pragma unroll
        for (int e = 0; e < E; e++) acc[e] += xv * g[e];
    }
#pragma unroll
    for (int e = 0; e < E; e++)
#pragma unroll
        for (int o = 16; o; o >>= 1) acc[e] += __shfl_xor_sync(0xffffffffu, acc[e], o);
    if (lane == 0) {
        int i1 = 0; float l1 = acc[0];
#pragma unroll
        for (int e = 1; e < E; e++) if (acc[e] > l1) { l1 = acc[e]; i1 = e; }
        int i2 = -1; float l2 = -INFINITY;
#pragma unroll
        for (int e = 0; e < E; e++) if (e != i1 && acc[e] > l2) { l2 = acc[e]; i2 = e; }
        float w1 = 1.f / (1.f + expf(l2 - l1));   // exact normalized top-2 softmax
        g_topi[2 * warp] = i1;  g_topi[2 * warp + 1] = i2;
        g_topw[2 * warp] = w1;  g_topw[2 * warp + 1] = 1.f - w1;
        atomicAdd(&g_cnt[i1], 1);
        atomicAdd(&g_cnt[i2], 1);
    }
}

// ---------------- scatter (with local prefix scan of 8 counts) -------------
__global__ void scatter_kernel() {
    __shared__ int soff[E + 1];
    if (threadIdx.x == 0) {
        int acc = 0;
#pragma unroll
        for (int e = 0; e < E; e++) { soff[e] = acc; acc += g_cnt[e]; }
        soff[E] = acc;
        if (blockIdx.x == 0) {
#pragma unroll
            for (int e = 0; e <= E; e++) g_off[e] = soff[e];
        }
    }
    __syncthreads();
    int t = blockIdx.x * blockDim.x + threadIdx.x;
    if (t >= T) return;
#pragma unroll
    for (int k = 0; k < 2; k++) {
        int e = g_topi[2 * t + k];
        int p = soff[e] + atomicAdd(&g_cur[e], 1);
        g_slot_token[p] = t;
        g_slot_e[p]     = e;
        g_slot_w[p]     = g_topw[2 * t + k];
        g_tok_slot[2 * t + k] = p;
    }
}

// ---------------- mma.sync grouped GEMM (fp16, 2 CTAs/SM) ------------------
// Block tile 128(M) x 128(N), K-chunk 32, 5 stages, 8 warps (4x2),
// warp tile 32x64. Small smem (95.7KB) -> 2 resident CTAs/SM so one CTA's
// MMA phase overlaps the other's LDSM/barrier phase (breaks the convoy).
// A smem: [128][32] fp16, row stride 80B (conflict-free ldmatrix)
// B smem: [32][128] fp16, row stride 272B (conflict-free ldmatrix.trans)
#define A_STRIDE 80
#define B_STRIDE 272
#define B_OFF    (128 * A_STRIDE)            // 10240
#define STAGE_SZ (B_OFF + 32 * B_STRIDE)     // 18944
#define NSTAGE   5
#define MM_SMEM  (1024 + NSTAGE * STAGE_SZ)  // 95744
#define NTHR     256

template <int NT, int KD, int MODE>
__global__ void __launch_bounds__(NTHR, 2) mma_gemm(const float* __restrict__ bias) {
    const int e    = blockIdx.z;
    const int base = g_off[e];
    const int cnt  = g_off[e + 1] - base;
    const int row0 = blockIdx.y * 128;
    if (row0 >= cnt) return;
    const int n0 = blockIdx.x * 128;

    extern __shared__ __align__(128) char smem[];
    const uint32_t sb = s2u(smem);
    int* rowidx = (int*)smem;
    const int tid = threadIdx.x, wid = tid >> 5, lane = tid & 31;

    const __half* __restrict__ Asrc = (MODE == 0) ? g_xf : g_act;
    const __half* __restrict__ Bsrc =
        ((MODE == 0) ? g_w1f : g_w2f) + (size_t)e * KD * NT + n0;

    if (tid < 128) {
        int r = row0 + tid; if (r > cnt - 1) r = cnt - 1;
        rowidx[tid] = (MODE == 0) ? g_slot_token[base + r] : (base + r);
    }
    __syncthreads();

    auto issue = [&](int c) {
        const int k0 = c * 32;
        const uint32_t s = sb + 1024 + (c % NSTAGE) * STAGE_SZ;
        // A: 128 rows x 64B (4x16B) = 512 xfers; 2 per thread
#pragma unroll
        for (int i = 0; i < 2; i++) {
            int idx = i * NTHR + tid;
            int row = idx >> 2, q = idx & 3;
            size_t go = (size_t)rowidx[row] * KD + k0 + q * 8;
            CP_ASYNC(s + row * A_STRIDE + q * 16, Asrc + go);
        }
        // B: 32 rows x 256B (16x16B) = 512 xfers; 2 per thread
#pragma unroll
        for (int i = 0; i < 2; i++) {
            int idx = i * NTHR + tid;
            int row = idx >> 4, q = idx & 15;
            size_t go = (size_t)(k0 + row) * NT + q * 8;
            CP_ASYNC(s + B_OFF + row * B_STRIDE + q * 16, Bsrc + go);
        }
        CP_COMMIT();
    };

    float acc[2][8][4];
#pragma unroll
    for (int i = 0; i < 2; i++)
#pragma unroll
        for (int j = 0; j < 8; j++)
#pragma unroll
            for (int q = 0; q < 4; q++) acc[i][j][q] = 0.f;

    const int warp_m = wid >> 1, warp_n = wid & 1;   // 4x2 warps, tile 32x64
    const int mat = lane >> 3, rin = lane & 7;
    const uint32_t aOffBase = (uint32_t)((warp_m * 32 + rin + (mat & 1) * 8) * A_STRIDE
                                         + (mat >> 1) * 16);
    const uint32_t bOffBase = (uint32_t)(B_OFF + ((mat & 1) * 8 + rin) * B_STRIDE
                                         + (warp_n * 64 + (mat >> 1) * 8) * 2);

    constexpr int NCH = KD / 32;
    issue(0); issue(1); issue(2); issue(3);

    for (int c = 0; c < NCH; c++) {
        CP_WAIT3();
        __syncthreads();
        const uint32_t s = sb + 1024 + (c % NSTAGE) * STAGE_SZ;
#pragma unroll
        for (int ks = 0; ks < 2; ks++) {
            uint32_t ah[2][4];
            uint32_t aAddr = s + aOffBase + ks * 32;
#pragma unroll
            for (int i = 0; i < 2; i++) LDSM4(ah[i], aAddr + i * 16 * A_STRIDE);
#pragma unroll
            for (int jh = 0; jh < 2; jh++) {
                uint32_t bh[4][2];
                uint32_t bAddr = s + bOffBase + ks * 16 * B_STRIDE + jh * 64;
                LDSM4T(&bh[0][0], bAddr);
                LDSM4T(&bh[2][0], bAddr + 32);
#pragma unroll
                for (int i = 0; i < 2; i++)
#pragma unroll
                    for (int j = 0; j < 4; j++) MMA(acc[i][jh * 4 + j], ah[i], bh[j]);
            }
        }
        if (c + 4 < NCH) issue(c + 4);
        else CP_COMMIT();
    }

    // epilogue: warp rows warp_m*32 + i*16 + lane/4 (+8), cols warp_n*64 + j*8
    const float* bp = bias + (size_t)e * NT;
#pragma unroll
    for (int i = 0; i < 2; i++) {
        int r1 = row0 + warp_m * 32 + i * 16 + (lane >> 2);
        int r2 = r1 + 8;
        bool v1 = r1 < cnt, v2 = r2 < cnt;
        float w1g = 1.f, w2g = 1.f;
        if (MODE == 1) {
            if (v1) w1g = g_slot_w[base + r1];
            if (v2) w2g = g_slot_w[base + r2];
        }
#pragma unroll
        for (int j = 0; j < 8; j++) {
            int col = n0 + warp_n * 64 + j * 8 + (lane & 3) * 2;
            float b0 = bp[col], b1 = bp[col + 1];
            if (MODE == 0) {
                if (v1) {
                    *(__half2*)(g_act + (size_t)(base + r1) * NT + col) =
                        __floats2half2_rn(acc[i][j][0] + b0, acc[i][j][1] + b1);
                }
                if (v2) {
                    *(__half2*)(g_act + (size_t)(base + r2) * NT + col) =
                        __floats2half2_rn(acc[i][j][2] + b0, acc[i][j][3] + b1);
                }
            } else {
                if (v1) {
                    float2 o = make_float2((acc[i][j][0] + b0) * w1g,
                                           (acc[i][j][1] + b1) * w1g);
                    *(float2*)(g_y + (size_t)(base + r1) * NT + col) = o;
                }
                if (v2) {
                    float2 o = make_float2((acc[i][j][2] + b0) * w2g,
                                           (acc[i][j][3] + b1) * w2g);
                    *(float2*)(g_y + (size_t)(base + r2) * NT + col) = o;
                }
            }
        }
    }
}

// ---------------- block reduction helper ----------------
__device__ __forceinline__ float2 block_reduce2(float a, float b) {
#pragma unroll
    for (int o = 16; o; o >>= 1) {
        a += __shfl_xor_sync(0xffffffffu, a, o);
        b += __shfl_xor_sync(0xffffffffu, b, o);
    }
    __shared__ float2 sm[8];
    int w = threadIdx.x >> 5, l = threadIdx.x & 31;
    if (l == 0) sm[w] = make_float2(a, b);
    __syncthreads();
    if (w == 0) {
        float2 v = (l < 8) ? sm[l] : make_float2(0.f, 0.f);
#pragma unroll
        for (int o = 4; o; o >>= 1) {
            v.x += __shfl_xor_sync(0xffffffffu, v.x, o);
            v.y += __shfl_xor_sync(0xffffffffu, v.y, o);
        }
        if (l == 0) sm[0] = v;
    }
    __syncthreads();
    return sm[0];
}

// ---------------- LN1 + exact GELU, in-place on fp16 g_act ----------------
__global__ __launch_bounds__(256) void ln_gelu_kernel(
    const float* __restrict__ ln1_g, const float* __restrict__ ln1_b) {
    int s = blockIdx.x;
    int e = g_slot_e[s];
    __half* row = g_act + (size_t)s * HDIM;
    int t = threadIdx.x;

    uint4 raw = ((const uint4*)row)[t];            // 8 halfs per thread
    __half2 h2[4];
    h2[0] = *(__half2*)&raw.x; h2[1] = *(__half2*)&raw.y;
    h2[2] = *(__half2*)&raw.z; h2[3] = *(__half2*)&raw.w;
    float va[8];
#pragma unroll
    for (int i = 0; i < 4; i++) {
        float2 f = __half22float2(h2[i]);
        va[2 * i] = f.x; va[2 * i + 1] = f.y;
    }
    float sum = 0.f, sq = 0.f;
#pragma unroll
    for (int i = 0; i < 8; i++) { sum += va[i]; sq += va[i] * va[i]; }
    float2 r = block_reduce2(sum, sq);
    float mean = r.x * (1.f / HDIM);
    float var  = r.y * (1.f / HDIM) - mean * mean;
    float rstd = rsqrtf(var + EPS);

    const float4 gg0 = ((const float4*)(ln1_g + (size_t)e * HDIM))[2 * t];
    const float4 gg1 = ((const float4*)(ln1_g + (size_t)e * HDIM))[2 * t + 1];
    const float4 bb0 = ((const float4*)(ln1_b + (size_t)e * HDIM))[2 * t];
    const float4 bb1 = ((const float4*)(ln1_b + (size_t)e * HDIM))[2 * t + 1];
    float ga[8] = {gg0.x, gg0.y, gg0.z, gg0.w, gg1.x, gg1.y, gg1.z, gg1.w};
    float ba[8] = {bb0.x, bb0.y, bb0.z, bb0.w, bb1.x, bb1.y, bb1.z, bb1.w};

    float gv[8];
#pragma unroll
    for (int i = 0; i < 8; i++) {
        float u = (va[i] - mean) * rstd * ga[i] + ba[i];
        gv[i] = 0.5f * u * (1.f + erff(u * 0.70710678118654752f));
    }
    uint4 outw;
    *(__half2*)&outw.x = __floats2half2_rn(gv[0], gv[1]);
    *(__half2*)&outw.y = __floats2half2_rn(gv[2], gv[3]);
    *(__half2*)&outw.z = __floats2half2_rn(gv[4], gv[5]);
    *(__half2*)&outw.w = __floats2half2_rn(gv[6], gv[7]);
    ((uint4*)row)[t] = outw;
}

// ---------------- combine: out = LN(x + y0 + y1) ----------------
__global__ __launch_bounds__(256) void combine_kernel(
    const float* __restrict__ x, const float* __restrict__ ln_g,
    const float* __restrict__ ln_b, float* __restrict__ outp) {
    int tkn = blockIdx.x;
    int s0 = g_tok_slot[2 * tkn], s1 = g_tok_slot[2 * tkn + 1];
    int t = threadIdx.x;

    float4 xv = ((const float4*)(x + (size_t)tkn * DIM))[t];
    float4 y0 = ((const float4*)(g_y + (size_t)s0 * DIM))[t];
    float4 y1 = ((const float4*)(g_y + (size_t)s1 * DIM))[t];
    float4 v = make_float4(xv.x + y0.x + y1.x, xv.y + y0.y + y1.y,
                           xv.z + y0.z + y1.z, xv.w + y0.w + y1.w);
    float sum = v.x + v.y + v.z + v.w;
    float sq  = v.x * v.x + v.y * v.y + v.z * v.z + v.w * v.w;
    float2 r = block_reduce2(sum, sq);
    float mean = r.x * (1.f / DIM);
    float var  = r.y * (1.f / DIM) - mean * mean;
    float rstd = rsqrtf(var + EPS);

    float4 gg = ((const float4*)ln_g)[t];
    float4 bb = ((const float4*)ln_b)[t];
    float4 o = make_float4((v.x - mean) * rstd * gg.x + bb.x,
                           (v.y - mean) * rstd * gg.y + bb.y,
                           (v.z - mean) * rstd * gg.z + bb.z,
                           (v.w - mean) * rstd * gg.w + bb.w);
    ((float4*)(outp + (size_t)tkn * DIM))[t] = o;
}

// ---------------- launch ----------------
extern "C" void kernel_launch(void* const* d_in, const int* in_sizes, int n_in,
                              void* d_out, int out_size) {
    const float* x      = (const float*)d_in[0];
    const float* gate_w = (const float*)d_in[1];
    const float* w1     = (const float*)d_in[2];
    const float* b1     = (const float*)d_in[3];
    const float* ln1_g  = (const float*)d_in[4];
    const float* ln1_b  = (const float*)d_in[5];
    const float* w2     = (const float*)d_in[6];
    const float* b2     = (const float*)d_in[7];
    const float* ln_g   = (const float*)d_in[8];
    const float* ln_b   = (const float*)d_in[9];
    float* outp = (float*)d_out;

    cudaFuncSetAttribute(mma_gemm<HDIM, DIM, 0>,
                         cudaFuncAttributeMaxDynamicSharedMemorySize, MM_SMEM);
    cudaFuncSetAttribute(mma_gemm<DIM, HDIM, 1>,
                         cudaFuncAttributeMaxDynamicSharedMemorySize, MM_SMEM);

    // fused: init counters + fp32->fp16 conversion of x, w1, w2
    prep_kernel<<<(int)((NPREP + 255) / 256), 256>>>(x, w1, w2);
    gate_kernel<<<T / 8, 256>>>(x, gate_w);
    scatter_kernel<<<T / 256, 256>>>();

    // GEMM1: gathered x @ w1 + b1 -> g_act (fp16)
    mma_gemm<HDIM, DIM, 0><<<dim3(HDIM / 128, T / 128, E), NTHR, MM_SMEM>>>(b1);
    ln_gelu_kernel<<<NSLOT, 256>>>(ln1_g, ln1_b);
    // GEMM2: act @ w2 + b2, gate-scaled -> g_y (fp32)
    mma_gemm<DIM, HDIM, 1><<<dim3(DIM / 128, T / 128, E), NTHR, MM_SMEM>>>(b2);
    combine_kernel<<<T, 256>>>(x, ln_g, ln_b, outp);
}

// round 16
// speedup vs baseline: 1.1281x; 1.0214x over previous
#include <cuda_runtime.h>
#include <cuda_fp16.h>
#include <math.h>
#include <stdint.h>

#define T      4096
#define DIM    1024
#define E      8
#define HDIM   2048
#define NSLOT  (T * 2)
#define EPS    1e-5f

// ---------------- device scratch (static, allocation-free) ----------------
__device__ __half g_y[(size_t)NSLOT * DIM];        // GEMM2 out (fp16, gate-scaled)
__device__ __half g_xf[(size_t)T * DIM];
__device__ __half g_act[(size_t)NSLOT * HDIM];     // GEMM1 out (fp16), LN+GELU in-place
__device__ __half g_w1f[(size_t)E * DIM * HDIM];   // [E][K=1024][N=2048]
__device__ __half g_w2f[(size_t)E * HDIM * DIM];   // [E][K=2048][N=1024]
__device__ int   g_cnt[E];
__device__ int   g_cur[E];
__device__ int   g_off[E + 1];
__device__ int   g_topi[NSLOT];
__device__ float g_topw[NSLOT];
__device__ int   g_slot_token[NSLOT];
__device__ int   g_slot_e[NSLOT];
__device__ float g_slot_w[NSLOT];
__device__ int   g_tok_slot[NSLOT];

// ---------------- PTX helpers ----------------
__device__ __forceinline__ uint32_t s2u(const void* p) {
    uint32_t a;
    asm("{ .reg .u64 t; cvta.to.shared.u64 t, %1; cvt.u32.u64 %0, t; }" : "=r"(a) : "l"(p));
    return a;
}

#define CP_ASYNC(sa, ga) \
    asm volatile("cp.async.cg.shared.global [%0], [%1], 16;" :: "r"(sa), "l"(ga))
#define CP_COMMIT() asm volatile("cp.async.commit_group;" ::: "memory")
#define CP_WAIT3()  asm volatile("cp.async.wait_group 3;" ::: "memory")

#define LDSM4(r, addr) \
    asm volatile("ldmatrix.sync.aligned.m8n8.x4.shared.b16 {%0,%1,%2,%3}, [%4];" \
        : "=r"((r)[0]), "=r"((r)[1]), "=r"((r)[2]), "=r"((r)[3]) : "r"(addr))
#define LDSM4T(r, addr) \
    asm volatile("ldmatrix.sync.aligned.m8n8.x4.trans.shared.b16 {%0,%1,%2,%3}, [%4];" \
        : "=r"((r)[0]), "=r"((r)[1]), "=r"((r)[2]), "=r"((r)[3]) : "r"(addr))

#define MMA(acc, a, b) \
    asm volatile("mma.sync.aligned.m16n8k16.row.col.f32.f16.f16.f32 " \
        "{%0,%1,%2,%3}, {%4,%5,%6,%7}, {%8,%9}, {%0,%1,%2,%3};" \
        : "+f"((acc)[0]), "+f"((acc)[1]), "+f"((acc)[2]), "+f"((acc)[3]) \
        : "r"((a)[0]), "r"((a)[1]), "r"((a)[2]), "r"((a)[3]), "r"((b)[0]), "r"((b)[1]))

// ---------------- prep: init counters + convert w1/w2 to fp16 --------------
#define NW4  ((size_t)E * DIM * HDIM / 4)
#define NPREP (2 * NW4)

__global__ void prep_kernel(const float* __restrict__ w1,
                            const float* __restrict__ w2) {
    size_t i = (size_t)blockIdx.x * blockDim.x + threadIdx.x;
    if (i < E) { g_cnt[i] = 0; g_cur[i] = 0; }
    if (i >= NPREP) return;
    const float* src;
    __half2* dst;
    size_t j;
    if (i < NW4) { src = w1; dst = (__half2*)g_w1f; j = i; }
    else         { src = w2; dst = (__half2*)g_w2f; j = i - NW4; }
    float4 v = ((const float4*)src)[j];
    dst[2 * j]     = __floats2half2_rn(v.x, v.y);
    dst[2 * j + 1] = __floats2half2_rn(v.z, v.w);
}

// ---------------- gating: one warp per token (+ separate x->fp16 pass) -----
__global__ void gate_kernel(const float* __restrict__ x, const float* __restrict__ gw) {
    int warp = (blockIdx.x * blockDim.x + threadIdx.x) >> 5;
    int lane = threadIdx.x & 31;
    if (warp >= T) return;
    const float* xr = x + (size_t)warp * DIM;
    float acc[E];
#pragma unroll
    for (int e = 0; e < E; e++) acc[e] = 0.f;
    for (int d = lane; d < DIM; d += 32) {
        float xv = xr[d];
        const float* g = gw + d * E;
#pragma unroll
        for (int e = 0; e < E; e++) acc[e] += xv * g[e];
    }
    // second pass (L1 hits): emit fp16 copy of x
    {
        __half2* xo = (__half2*)(g_xf + (size_t)warp * DIM);
        const float2* xr2 = (const float2*)xr;
        for (int d2 = lane; d2 < DIM / 2; d2 += 32) {
            float2 v = xr2[d2];
            xo[d2] = __floats2half2_rn(v.x, v.y);
        }
    }
#pragma unroll
    for (int e = 0; e < E; e++)
#pragma unroll
        for (int o = 16; o; o >>= 1) acc[e] += __shfl_xor_sync(0xffffffffu, acc[e], o);
    if (lane == 0) {
        int i1 = 0; float l1 = acc[0];
#pragma unroll
        for (int e = 1; e < E; e++) if (acc[e] > l1) { l1 = acc[e]; i1 = e; }
        int i2 = -1; float l2 = -INFINITY;
#pragma unroll
        for (int e = 0; e < E; e++) if (e != i1 && acc[e] > l2) { l2 = acc[e]; i2 = e; }
        float w1 = 1.f / (1.f + expf(l2 - l1));   // exact normalized top-2 softmax
        g_topi[2 * warp] = i1;  g_topi[2 * warp + 1] = i2;
        g_topw[2 * warp] = w1;  g_topw[2 * warp + 1] = 1.f - w1;
        atomicAdd(&g_cnt[i1], 1);
        atomicAdd(&g_cnt[i2], 1);
    }
}

// ---------------- scatter (with local prefix scan of 8 counts) -------------
__global__ void scatter_kernel() {
    __shared__ int soff[E + 1];
    if (threadIdx.x == 0) {
        int acc = 0;
#pragma unroll
        for (int e = 0; e < E; e++) { soff[e] = acc; acc += g_cnt[e]; }
        soff[E] = acc;
        if (blockIdx.x == 0) {
#pragma unroll
            for (int e = 0; e <= E; e++) g_off[e] = soff[e];
        }
    }
    __syncthreads();
    int t = blockIdx.x * blockDim.x + threadIdx.x;
    if (t >= T) return;
#pragma unroll
    for (int k = 0; k < 2; k++) {
        int e = g_topi[2 * t + k];
        int p = soff[e] + atomicAdd(&g_cur[e], 1);
        g_slot_token[p] = t;
        g_slot_e[p]     = e;
        g_slot_w[p]     = g_topw[2 * t + k];
        g_tok_slot[2 * t + k] = p;
    }
}

// ---------------- mma.sync grouped GEMM (fp16, 2 CTAs/SM) ------------------
// Block tile 128(M) x 128(N), K-chunk 32, 5 stages, 8 warps (4x2),
// warp tile 32x64. 95.7KB smem -> 2 resident CTAs/SM (convoy-breaking).
// A smem: [128][32] fp16, row stride 80B (conflict-free ldmatrix)
// B smem: [32][128] fp16, row stride 272B (conflict-free ldmatrix.trans)
#define A_STRIDE 80
#define B_STRIDE 272
#define B_OFF    (128 * A_STRIDE)            // 10240
#define STAGE_SZ (B_OFF + 32 * B_STRIDE)     // 18944
#define NSTAGE   5
#define MM_SMEM  (1024 + NSTAGE * STAGE_SZ)  // 95744
#define NTHR     256

template <int NT, int KD, int MODE>
__global__ void __launch_bounds__(NTHR, 2) mma_gemm(const float* __restrict__ bias) {
    const int e    = blockIdx.z;
    const int base = g_off[e];
    const int cnt  = g_off[e + 1] - base;
    const int row0 = blockIdx.y * 128;
    if (row0 >= cnt) return;
    const int n0 = blockIdx.x * 128;

    extern __shared__ __align__(128) char smem[];
    const uint32_t sb = s2u(smem);
    int* rowidx = (int*)smem;
    const int tid = threadIdx.x, wid = tid >> 5, lane = tid & 31;

    const __half* __restrict__ Asrc = (MODE == 0) ? g_xf : g_act;
    const __half* __restrict__ Bsrc =
        ((MODE == 0) ? g_w1f : g_w2f) + (size_t)e * KD * NT + n0;

    if (tid < 128) {
        int r = row0 + tid; if (r > cnt - 1) r = cnt - 1;
        rowidx[tid] = (MODE == 0) ? g_slot_token[base + r] : (base + r);
    }
    __syncthreads();

    auto issue = [&](int c) {
        const int k0 = c * 32;
        const uint32_t s = sb + 1024 + (c % NSTAGE) * STAGE_SZ;
        // A: 128 rows x 64B (4x16B) = 512 xfers; 2 per thread
#pragma unroll
        for (int i = 0; i < 2; i++) {
            int idx = i * NTHR + tid;
            int row = idx >> 2, q = idx & 3;
            size_t go = (size_t)rowidx[row] * KD + k0 + q * 8;
            CP_ASYNC(s + row * A_STRIDE + q * 16, Asrc + go);
        }
        // B: 32 rows x 256B (16x16B) = 512 xfers; 2 per thread
#pragma unroll
        for (int i = 0; i < 2; i++) {
            int idx = i * NTHR + tid;
            int row = idx >> 4, q = idx & 15;
            size_t go = (size_t)(k0 + row) * NT + q * 8;
            CP_ASYNC(s + B_OFF + row * B_STRIDE + q * 16, Bsrc + go);
        }
        CP_COMMIT();
    };

    float acc[2][8][4];
#pragma unroll
    for (int i = 0; i < 2; i++)
#pragma unroll
        for (int j = 0; j < 8; j++)
#pragma unroll
            for (int q = 0; q < 4; q++) acc[i][j][q] = 0.f;

    const int warp_m = wid >> 1, warp_n = wid & 1;   // 4x2 warps, tile 32x64
    const int mat = lane >> 3, rin = lane & 7;
    const uint32_t aOffBase = (uint32_t)((warp_m * 32 + rin + (mat & 1) * 8) * A_STRIDE
                                         + (mat >> 1) * 16);
    const uint32_t bOffBase = (uint32_t)(B_OFF + ((mat & 1) * 8 + rin) * B_STRIDE
                                         + (warp_n * 64 + (mat >> 1) * 8) * 2);

    constexpr int NCH = KD / 32;
    issue(0); issue(1); issue(2); issue(3);

    for (int c = 0; c < NCH; c++) {
        CP_WAIT3();
        __syncthreads();
        const uint32_t s = sb + 1024 + (c % NSTAGE) * STAGE_SZ;
#pragma unroll
        for (int ks = 0; ks < 2; ks++) {
            uint32_t ah[2][4];
            uint32_t aAddr = s + aOffBase + ks * 32;
#pragma unroll
            for (int i = 0; i < 2; i++) LDSM4(ah[i], aAddr + i * 16 * A_STRIDE);
#pragma unroll
            for (int jh = 0; jh < 2; jh++) {
                uint32_t bh[4][2];
                uint32_t bAddr = s + bOffBase + ks * 16 * B_STRIDE + jh * 64;
                LDSM4T(&bh[0][0], bAddr);
                LDSM4T(&bh[2][0], bAddr + 32);
#pragma unroll
                for (int i = 0; i < 2; i++)
#pragma unroll
                    for (int j = 0; j < 4; j++) MMA(acc[i][jh * 4 + j], ah[i], bh[j]);
            }
        }
        if (c + 4 < NCH) issue(c + 4);
        else CP_COMMIT();
    }

    // epilogue: warp rows warp_m*32 + i*16 + lane/4 (+8), cols warp_n*64 + j*8
    const float* bp = bias + (size_t)e * NT;
#pragma unroll
    for (int i = 0; i < 2; i++) {
        int r1 = row0 + warp_m * 32 + i * 16 + (lane >> 2);
        int r2 = r1 + 8;
        bool v1 = r1 < cnt, v2 = r2 < cnt;
        float w1g = 1.f, w2g = 1.f;
        if (MODE == 1) {
            if (v1) w1g = g_slot_w[base + r1];
            if (v2) w2g = g_slot_w[base + r2];
        }
#pragma unroll
        for (int j = 0; j < 8; j++) {
            int col = n0 + warp_n * 64 + j * 8 + (lane & 3) * 2;
            float b0 = bp[col], b1 = bp[col + 1];
            if (MODE == 0) {
                if (v1) {
                    *(__half2*)(g_act + (size_t)(base + r1) * NT + col) =
                        __floats2half2_rn(acc[i][j][0] + b0, acc[i][j][1] + b1);
                }
                if (v2) {
                    *(__half2*)(g_act + (size_t)(base + r2) * NT + col) =
                        __floats2half2_rn(acc[i][j][2] + b0, acc[i][j][3] + b1);
                }
            } else {
                if (v1) {
                    *(__half2*)(g_y + (size_t)(base + r1) * NT + col) =
                        __floats2half2_rn((acc[i][j][0] + b0) * w1g,
                                          (acc[i][j][1] + b1) * w1g);
                }
                if (v2) {
                    *(__half2*)(g_y + (size_t)(base + r2) * NT + col) =
                        __floats2half2_rn((acc[i][j][2] + b0) * w2g,
                                          (acc[i][j][3] + b1) * w2g);
                }
            }
        }
    }
}

// ---------------- block reduction helper ----------------
__device__ __forceinline__ float2 block_reduce2(float a, float b) {
#pragma unroll
    for (int o = 16; o; o >>= 1) {
        a += __shfl_xor_sync(0xffffffffu, a, o);
        b += __shfl_xor_sync(0xffffffffu, b, o);
    }
    __shared__ float2 sm[8];
    int w = threadIdx.x >> 5, l = threadIdx.x & 31;
    if (l == 0) sm[w] = make_float2(a, b);
    __syncthreads();
    if (w == 0) {
        float2 v = (l < 8) ? sm[l] : make_float2(0.f, 0.f);
#pragma unroll
        for (int o = 4; o; o >>= 1) {
            v.x += __shfl_xor_sync(0xffffffffu, v.x, o);
            v.y += __shfl_xor_sync(0xffffffffu, v.y, o);
        }
        if (l == 0) sm[0] = v;
    }
    __syncthreads();
    return sm[0];
}

// ---------------- LN1 + exact GELU, in-place on fp16 g_act ----------------
__global__ __launch_bounds__(256) void ln_gelu_kernel(
    const float* __restrict__ ln1_g, const float* __restrict__ ln1_b) {
    int s = blockIdx.x;
    int e = g_slot_e[s];
    __half* row = g_act + (size_t)s * HDIM;
    int t = threadIdx.x;

    uint4 raw = ((const uint4*)row)[t];            // 8 halfs per thread
    __half2 h2[4];
    h2[0] = *(__half2*)&raw.x; h2[1] = *(__half2*)&raw.y;
    h2[2] = *(__half2*)&raw.z; h2[3] = *(__half2*)&raw.w;
    float va[8];
#pragma unroll
    for (int i = 0; i < 4; i++) {
        float2 f = __half22float2(h2[i]);
        va[2 * i] = f.x; va[2 * i + 1] = f.y;
    }
    float sum = 0.f, sq = 0.f;
#pragma unroll
    for (int i = 0; i < 8; i++) { sum += va[i]; sq += va[i] * va[i]; }
    float2 r = block_reduce2(sum, sq);
    float mean = r.x * (1.f / HDIM);
    float var  = r.y * (1.f / HDIM) - mean * mean;
    float rstd = rsqrtf(var + EPS);

    const float4 gg0 = ((const float4*)(ln1_g + (size_t)e * HDIM))[2 * t];
    const float4 gg1 = ((const float4*)(ln1_g + (size_t)e * HDIM))[2 * t + 1];
    const float4 bb0 = ((const float4*)(ln1_b + (size_t)e * HDIM))[2 * t];
    const float4 bb1 = ((const float4*)(ln1_b + (size_t)e * HDIM))[2 * t + 1];
    float ga[8] = {gg0.x, gg0.y, gg0.z, gg0.w, gg1.x, gg1.y, gg1.z, gg1.w};
    float ba[8] = {bb0.x, bb0.y, bb0.z, bb0.w, bb1.x, bb1.y, bb1.z, bb1.w};

    float gv[8];
#pragma unroll
    for (int i = 0; i < 8; i++) {
        float u = (va[i] - mean) * rstd * ga[i] + ba[i];
        gv[i] = 0.5f * u * (1.f + erff(u * 0.70710678118654752f));
    }
    uint4 outw;
    *(__half2*)&outw.x = __floats2half2_rn(gv[0], gv[1]);
    *(__half2*)&outw.y = __floats2half2_rn(gv[2], gv[3]);
    *(__half2*)&outw.z = __floats2half2_rn(gv[4], gv[5]);
    *(__half2*)&outw.w = __floats2half2_rn(gv[6], gv[7]);
    ((uint4*)row)[t] = outw;
}

// ---------------- combine: out = LN(x + y0 + y1), y in fp16 ----------------
__global__ __launch_bounds__(256) void combine_kernel(
    const float* __restrict__ x, const float* __restrict__ ln_g,
    const float* __restrict__ ln_b, float* __restrict__ outp) {
    int tkn = blockIdx.x;
    int s0 = g_tok_slot[2 * tkn], s1 = g_tok_slot[2 * tkn + 1];
    int t = threadIdx.x;

    float4 xv = ((const float4*)(x + (size_t)tkn * DIM))[t];
    const __half2* y0p = (const __half2*)(g_y + (size_t)s0 * DIM);
    const __half2* y1p = (const __half2*)(g_y + (size_t)s1 * DIM);
    float2 ya = __half22float2(y0p[2 * t]);
    float2 yb = __half22float2(y0p[2 * t + 1]);
    float2 yc = __half22float2(y1p[2 * t]);
    float2 yd = __half22float2(y1p[2 * t + 1]);
    float4 v = make_float4(xv.x + ya.x + yc.x, xv.y + ya.y + yc.y,
                           xv.z + yb.x + yd.x, xv.w + yb.y + yd.y);
    float sum = v.x + v.y + v.z + v.w;
    float sq  = v.x * v.x + v.y * v.y + v.z * v.z + v.w * v.w;
    float2 r = block_reduce2(sum, sq);
    float mean = r.x * (1.f / DIM);
    float var  = r.y * (1.f / DIM) - mean * mean;
    float rstd = rsqrtf(var + EPS);

    float4 gg = ((const float4*)ln_g)[t];
    float4 bb = ((const float4*)ln_b)[t];
    float4 o = make_float4((v.x - mean) * rstd * gg.x + bb.x,
                           (v.y - mean) * rstd * gg.y + bb.y,
                           (v.z - mean) * rstd * gg.z + bb.z,
                           (v.w - mean) * rstd * gg.w + bb.w);
    ((float4*)(outp + (size_t)tkn * DIM))[t] = o;
}

// ---------------- launch ----------------
extern "C" void kernel_launch(void* const* d_in, const int* in_sizes, int n_in,
                              void* d_out, int out_size) {
    const float* x      = (const float*)d_in[0];
    const float* gate_w = (const float*)d_in[1];
    const float* w1     = (const float*)d_in[2];
    const float* b1     = (const float*)d_in[3];
    const float* ln1_g  = (const float*)d_in[4];
    const float* ln1_b  = (const float*)d_in[5];
    const float* w2     = (const float*)d_in[6];
    const float* b2     = (const float*)d_in[7];
    const float* ln_g   = (const float*)d_in[8];
    const float* ln_b   = (const float*)d_in[9];
    float* outp = (float*)d_out;

    cudaFuncSetAttribute(mma_gemm<HDIM, DIM, 0>,
                         cudaFuncAttributeMaxDynamicSharedMemorySize, MM_SMEM);
    cudaFuncSetAttribute(mma_gemm<DIM, HDIM, 1>,
                         cudaFuncAttributeMaxDynamicSharedMemorySize, MM_SMEM);

    // prep: init counters + fp32->fp16 conversion of w1, w2
    prep_kernel<<<(int)((NPREP + 255) / 256), 256>>>(w1, w2);
    // gate: routing + separate-pass x->fp16 emit
    gate_kernel<<<T / 8, 256>>>(x, gate_w);
    scatter_kernel<<<T / 256, 256>>>();

    // GEMM1: gathered x @ w1 + b1 -> g_act (fp16)
    mma_gemm<HDIM, DIM, 0><<<dim3(HDIM / 128, T / 128, E), NTHR, MM_SMEM>>>(b1);
    ln_gelu_kernel<<<NSLOT, 256>>>(ln1_g, ln1_b);
    // GEMM2: act @ w2 + b2, gate-scaled -> g_y (fp16)
    mma_gemm<DIM, HDIM, 1><<<dim3(DIM / 128, T / 128, E), NTHR, MM_SMEM>>>(b2);
    combine_kernel<<<T, 256>>>(x, ln_g, ln_b, outp);
}

// round 17
// speedup vs baseline: 1.1328x; 1.0042x over previous
#include <cuda_runtime.h>
#include <cuda_fp16.h>
#include <math.h>
#include <stdint.h>

#define T      4096
#define DIM    1024
#define E      8
#define HDIM   2048
#define NSLOT  (T * 2)
#define EPS    1e-5f

// ---------------- device scratch (static, allocation-free) ----------------
__device__ __half g_y[(size_t)NSLOT * DIM];        // GEMM2 out (fp16, gate-scaled)
__device__ __half g_xf[(size_t)T * DIM];
__device__ __half g_act[(size_t)NSLOT * HDIM];     // GEMM1 out (fp16), LN+GELU in-place
__device__ __half g_w1f[(size_t)E * DIM * HDIM];   // [E][K=1024][N=2048]
__device__ __half g_w2f[(size_t)E * HDIM * DIM];   // [E][K=2048][N=1024]
__device__ int   g_cnt[E];                          // static zero-init; reset by combine
__device__ int   g_cur[E];
__device__ int   g_off[E + 1];
__device__ int   g_topi[NSLOT];
__device__ float g_topw[NSLOT];
__device__ int   g_slot_token[NSLOT];
__device__ int   g_slot_e[NSLOT];
__device__ float g_slot_w[NSLOT];
__device__ int   g_tok_slot[NSLOT];

// ---------------- PTX helpers ----------------
__device__ __forceinline__ uint32_t s2u(const void* p) {
    uint32_t a;
    asm("{ .reg .u64 t; cvta.to.shared.u64 t, %1; cvt.u32.u64 %0, t; }" : "=r"(a) : "l"(p));
    return a;
}

#define CP_ASYNC(sa, ga) \
    asm volatile("cp.async.cg.shared.global [%0], [%1], 16;" :: "r"(sa), "l"(ga))
#define CP_COMMIT() asm volatile("cp.async.commit_group;" ::: "memory")
#define CP_WAIT3()  asm volatile("cp.async.wait_group 3;" ::: "memory")

#define LDSM4(r, addr) \
    asm volatile("ldmatrix.sync.aligned.m8n8.x4.shared.b16 {%0,%1,%2,%3}, [%4];" \
        : "=r"((r)[0]), "=r"((r)[1]), "=r"((r)[2]), "=r"((r)[3]) : "r"(addr))
#define LDSM4T(r, addr) \
    asm volatile("ldmatrix.sync.aligned.m8n8.x4.trans.shared.b16 {%0,%1,%2,%3}, [%4];" \
        : "=r"((r)[0]), "=r"((r)[1]), "=r"((r)[2]), "=r"((r)[3]) : "r"(addr))

#define MMA(acc, a, b) \
    asm volatile("mma.sync.aligned.m16n8k16.row.col.f32.f16.f16.f32 " \
        "{%0,%1,%2,%3}, {%4,%5,%6,%7}, {%8,%9}, {%0,%1,%2,%3};" \
        : "+f"((acc)[0]), "+f"((acc)[1]), "+f"((acc)[2]), "+f"((acc)[3]) \
        : "r"((a)[0]), "r"((a)[1]), "r"((a)[2]), "r"((a)[3]), "r"((b)[0]), "r"((b)[1]))

#define NW4       ((size_t)E * DIM * HDIM / 4)      // float4s per weight matrix
#define WCONV_CTA ((int)(NW4 / 256))                // 16384 CTAs per weight
#define GATE_CTA  (T / 8)                           // 512

// ---------------- gate (+ fused w1 fp32->fp16 conversion blocks) -----------
__global__ void gate_w1_kernel(const float* __restrict__ x,
                               const float* __restrict__ gw,
                               const float* __restrict__ w1) {
    if (blockIdx.x >= GATE_CTA) {
        // w1 conversion blocks
        size_t j = (size_t)(blockIdx.x - GATE_CTA) * blockDim.x + threadIdx.x;
        float4 v = ((const float4*)w1)[j];
        __half2* dst = (__half2*)g_w1f;
        dst[2 * j]     = __floats2half2_rn(v.x, v.y);
        dst[2 * j + 1] = __floats2half2_rn(v.z, v.w);
        return;
    }
    // gate blocks: one warp per token
    int warp = (blockIdx.x * blockDim.x + threadIdx.x) >> 5;
    int lane = threadIdx.x & 31;
    const float* xr = x + (size_t)warp * DIM;
    float acc[E];
#pragma unroll
    for (int e = 0; e < E; e++) acc[e] = 0.f;
    for (int d = lane; d < DIM; d += 32) {
        float xv = xr[d];
        const float* g = gw + d * E;
#pragma unroll
        for (int e = 0; e < E; e++) acc[e] += xv * g[e];
    }
    // second pass (L1 hits): emit fp16 copy of x
    {
        __half2* xo = (__half2*)(g_xf + (size_t)warp * DIM);
        const float2* xr2 = (const float2*)xr;
        for (int d2 = lane; d2 < DIM / 2; d2 += 32) {
            float2 v = xr2[d2];
            xo[d2] = __floats2half2_rn(v.x, v.y);
        }
    }
#pragma unroll
    for (int e = 0; e < E; e++)
#pragma unroll
        for (int o = 16; o; o >>= 1) acc[e] += __shfl_xor_sync(0xffffffffu, acc[e], o);
    if (lane == 0) {
        int i1 = 0; float l1 = acc[0];
#pragma unroll
        for (int e = 1; e < E; e++) if (acc[e] > l1) { l1 = acc[e]; i1 = e; }
        int i2 = -1; float l2 = -INFINITY;
#pragma unroll
        for (int e = 0; e < E; e++) if (e != i1 && acc[e] > l2) { l2 = acc[e]; i2 = e; }
        float w1v = 1.f / (1.f + expf(l2 - l1));   // exact normalized top-2 softmax
        g_topi[2 * warp] = i1;  g_topi[2 * warp + 1] = i2;
        g_topw[2 * warp] = w1v; g_topw[2 * warp + 1] = 1.f - w1v;
        atomicAdd(&g_cnt[i1], 1);
        atomicAdd(&g_cnt[i2], 1);
    }
}

// ---------------- scatter (with local prefix scan of 8 counts) -------------
__global__ void scatter_kernel() {
    __shared__ int soff[E + 1];
    if (threadIdx.x == 0) {
        int acc = 0;
#pragma unroll
        for (int e = 0; e < E; e++) { soff[e] = acc; acc += g_cnt[e]; }
        soff[E] = acc;
        if (blockIdx.x == 0) {
#pragma unroll
            for (int e = 0; e <= E; e++) g_off[e] = soff[e];
        }
    }
    __syncthreads();
    int t = blockIdx.x * blockDim.x + threadIdx.x;
    if (t >= T) return;
#pragma unroll
    for (int k = 0; k < 2; k++) {
        int e = g_topi[2 * t + k];
        int p = soff[e] + atomicAdd(&g_cur[e], 1);
        g_slot_token[p] = t;
        g_slot_e[p]     = e;
        g_slot_w[p]     = g_topw[2 * t + k];
        g_tok_slot[2 * t + k] = p;
    }
}

// ---------------- mma.sync grouped GEMM (fp16, 2 CTAs/SM) ------------------
// Block tile 128(M) x 128(N), K-chunk 32, 5 stages, 8 warps (4x2),
// warp tile 32x64. 95.7KB smem -> 2 resident CTAs/SM (convoy-breaking).
#define A_STRIDE 80
#define B_STRIDE 272
#define B_OFF    (128 * A_STRIDE)            // 10240
#define STAGE_SZ (B_OFF + 32 * B_STRIDE)     // 18944
#define NSTAGE   5
#define MM_SMEM  (1024 + NSTAGE * STAGE_SZ)  // 95744
#define NTHR     256

template <int NT, int KD, int MODE>
__global__ void __launch_bounds__(NTHR, 2) mma_gemm(const float* __restrict__ bias) {
    const int e    = blockIdx.z;
    const int base = g_off[e];
    const int cnt  = g_off[e + 1] - base;
    const int row0 = blockIdx.y * 128;
    if (row0 >= cnt) return;
    const int n0 = blockIdx.x * 128;

    extern __shared__ __align__(128) char smem[];
    const uint32_t sb = s2u(smem);
    int* rowidx = (int*)smem;
    const int tid = threadIdx.x, wid = tid >> 5, lane = tid & 31;

    const __half* __restrict__ Asrc = (MODE == 0) ? g_xf : g_act;
    const __half* __restrict__ Bsrc =
        ((MODE == 0) ? g_w1f : g_w2f) + (size_t)e * KD * NT + n0;

    if (tid < 128) {
        int r = row0 + tid; if (r > cnt - 1) r = cnt - 1;
        rowidx[tid] = (MODE == 0) ? g_slot_token[base + r] : (base + r);
    }
    __syncthreads();

    auto issue = [&](int c) {
        const int k0 = c * 32;
        const uint32_t s = sb + 1024 + (c % NSTAGE) * STAGE_SZ;
#pragma unroll
        for (int i = 0; i < 2; i++) {
            int idx = i * NTHR + tid;
            int row = idx >> 2, q = idx & 3;
            size_t go = (size_t)rowidx[row] * KD + k0 + q * 8;
            CP_ASYNC(s + row * A_STRIDE + q * 16, Asrc + go);
        }
#pragma unroll
        for (int i = 0; i < 2; i++) {
            int idx = i * NTHR + tid;
            int row = idx >> 4, q = idx & 15;
            size_t go = (size_t)(k0 + row) * NT + q * 8;
            CP_ASYNC(s + B_OFF + row * B_STRIDE + q * 16, Bsrc + go);
        }
        CP_COMMIT();
    };

    float acc[2][8][4];
#pragma unroll
    for (int i = 0; i < 2; i++)
#pragma unroll
        for (int j = 0; j < 8; j++)
#pragma unroll
            for (int q = 0; q < 4; q++) acc[i][j][q] = 0.f;

    const int warp_m = wid >> 1, warp_n = wid & 1;   // 4x2 warps, tile 32x64
    const int mat = lane >> 3, rin = lane & 7;
    const uint32_t aOffBase = (uint32_t)((warp_m * 32 + rin + (mat & 1) * 8) * A_STRIDE
                                         + (mat >> 1) * 16);
    const uint32_t bOffBase = (uint32_t)(B_OFF + ((mat & 1) * 8 + rin) * B_STRIDE
                                         + (warp_n * 64 + (mat >> 1) * 8) * 2);

    constexpr int NCH = KD / 32;
    issue(0); issue(1); issue(2); issue(3);

    for (int c = 0; c < NCH; c++) {
        CP_WAIT3();
        __syncthreads();
        const uint32_t s = sb + 1024 + (c % NSTAGE) * STAGE_SZ;
#pragma unroll
        for (int ks = 0; ks < 2; ks++) {
            uint32_t ah[2][4];
            uint32_t aAddr = s + aOffBase + ks * 32;
#pragma unroll
            for (int i = 0; i < 2; i++) LDSM4(ah[i], aAddr + i * 16 * A_STRIDE);
#pragma unroll
            for (int jh = 0; jh < 2; jh++) {
                uint32_t bh[4][2];
                uint32_t bAddr = s + bOffBase + ks * 16 * B_STRIDE + jh * 64;
                LDSM4T(&bh[0][0], bAddr);
                LDSM4T(&bh[2][0], bAddr + 32);
#pragma unroll
                for (int i = 0; i < 2; i++)
#pragma unroll
                    for (int j = 0; j < 4; j++) MMA(acc[i][jh * 4 + j], ah[i], bh[j]);
            }
        }
        if (c + 4 < NCH) issue(c + 4);
        else CP_COMMIT();
    }

    // epilogue
    const float* bp = bias + (size_t)e * NT;
#pragma unroll
    for (int i = 0; i < 2; i++) {
        int r1 = row0 + warp_m * 32 + i * 16 + (lane >> 2);
        int r2 = r1 + 8;
        bool v1 = r1 < cnt, v2 = r2 < cnt;
        float w1g = 1.f, w2g = 1.f;
        if (MODE == 1) {
            if (v1) w1g = g_slot_w[base + r1];
            if (v2) w2g = g_slot_w[base + r2];
        }
#pragma unroll
        for (int j = 0; j < 8; j++) {
            int col = n0 + warp_n * 64 + j * 8 + (lane & 3) * 2;
            float b0 = bp[col], b1 = bp[col + 1];
            if (MODE == 0) {
                if (v1) {
                    *(__half2*)(g_act + (size_t)(base + r1) * NT + col) =
                        __floats2half2_rn(acc[i][j][0] + b0, acc[i][j][1] + b1);
                }
                if (v2) {
                    *(__half2*)(g_act + (size_t)(base + r2) * NT + col) =
                        __floats2half2_rn(acc[i][j][2] + b0, acc[i][j][3] + b1);
                }
            } else {
                if (v1) {
                    *(__half2*)(g_y + (size_t)(base + r1) * NT + col) =
                        __floats2half2_rn((acc[i][j][0] + b0) * w1g,
                                          (acc[i][j][1] + b1) * w1g);
                }
                if (v2) {
                    *(__half2*)(g_y + (size_t)(base + r2) * NT + col) =
                        __floats2half2_rn((acc[i][j][2] + b0) * w2g,
                                          (acc[i][j][3] + b1) * w2g);
                }
            }
        }
    }
}

// ---------------- block reduction helper ----------------
__device__ __forceinline__ float2 block_reduce2(float a, float b) {
#pragma unroll
    for (int o = 16; o; o >>= 1) {
        a += __shfl_xor_sync(0xffffffffu, a, o);
        b += __shfl_xor_sync(0xffffffffu, b, o);
    }
    __shared__ float2 sm[8];
    int w = threadIdx.x >> 5, l = threadIdx.x & 31;
    if (l == 0) sm[w] = make_float2(a, b);
    __syncthreads();
    if (w == 0) {
        float2 v = (l < 8) ? sm[l] : make_float2(0.f, 0.f);
#pragma unroll
        for (int o = 4; o; o >>= 1) {
            v.x += __shfl_xor_sync(0xffffffffu, v.x, o);
            v.y += __shfl_xor_sync(0xffffffffu, v.y, o);
        }
        if (l == 0) sm[0] = v;
    }
    __syncthreads();
    return sm[0];
}

// ---------------- LN1 + exact GELU in-place (+ fused w2 conversion) --------
__global__ __launch_bounds__(256) void lngelu_w2_kernel(
    const float* __restrict__ ln1_g, const float* __restrict__ ln1_b,
    const float* __restrict__ w2) {
    if (blockIdx.x >= NSLOT) {
        // w2 conversion blocks
        size_t j = (size_t)(blockIdx.x - NSLOT) * blockDim.x + threadIdx.x;
        float4 v = ((const float4*)w2)[j];
        __half2* dst = (__half2*)g_w2f;
        dst[2 * j]     = __floats2half2_rn(v.x, v.y);
        dst[2 * j + 1] = __floats2half2_rn(v.z, v.w);
        return;
    }
    int s = blockIdx.x;
    int e = g_slot_e[s];
    __half* row = g_act + (size_t)s * HDIM;
    int t = threadIdx.x;

    uint4 raw = ((const uint4*)row)[t];            // 8 halfs per thread
    __half2 h2[4];
    h2[0] = *(__half2*)&raw.x; h2[1] = *(__half2*)&raw.y;
    h2[2] = *(__half2*)&raw.z; h2[3] = *(__half2*)&raw.w;
    float va[8];
#pragma unroll
    for (int i = 0; i < 4; i++) {
        float2 f = __half22float2(h2[i]);
        va[2 * i] = f.x; va[2 * i + 1] = f.y;
    }
    float sum = 0.f, sq = 0.f;
#pragma unroll
    for (int i = 0; i < 8; i++) { sum += va[i]; sq += va[i] * va[i]; }
    float2 r = block_reduce2(sum, sq);
    float mean = r.x * (1.f / HDIM);
    float var  = r.y * (1.f / HDIM) - mean * mean;
    float rstd = rsqrtf(var + EPS);

    const float4 gg0 = ((const float4*)(ln1_g + (size_t)e * HDIM))[2 * t];
    const float4 gg1 = ((const float4*)(ln1_g + (size_t)e * HDIM))[2 * t + 1];
    const float4 bb0 = ((const float4*)(ln1_b + (size_t)e * HDIM))[2 * t];
    const float4 bb1 = ((const float4*)(ln1_b + (size_t)e * HDIM))[2 * t + 1];
    float ga[8] = {gg0.x, gg0.y, gg0.z, gg0.w, gg1.x, gg1.y, gg1.z, gg1.w};
    float ba[8] = {bb0.x, bb0.y, bb0.z, bb0.w, bb1.x, bb1.y, bb1.z, bb1.w};

    float gv[8];
#pragma unroll
    for (int i = 0; i < 8; i++) {
        float u = (va[i] - mean) * rstd * ga[i] + ba[i];
        gv[i] = 0.5f * u * (1.f + erff(u * 0.70710678118654752f));
    }
    uint4 outw;
    *(__half2*)&outw.x = __floats2half2_rn(gv[0], gv[1]);
    *(__half2*)&outw.y = __floats2half2_rn(gv[2], gv[3]);
    *(__half2*)&outw.z = __floats2half2_rn(gv[4], gv[5]);
    *(__half2*)&outw.w = __floats2half2_rn(gv[6], gv[7]);
    ((uint4*)row)[t] = outw;
}

// ---------------- combine: out = LN(x + y0 + y1), y fp16; reset counters ---
__global__ __launch_bounds__(256) void combine_kernel(
    const float* __restrict__ x, const float* __restrict__ ln_g,
    const float* __restrict__ ln_b, float* __restrict__ outp) {
    int tkn = blockIdx.x;
    // reset routing counters for the next graph replay (deterministic restart)
    if (tkn == 0 && threadIdx.x < E) { g_cnt[threadIdx.x] = 0; g_cur[threadIdx.x] = 0; }
    int s0 = g_tok_slot[2 * tkn], s1 = g_tok_slot[2 * tkn + 1];
    int t = threadIdx.x;

    float4 xv = ((const float4*)(x + (size_t)tkn * DIM))[t];
    const __half2* y0p = (const __half2*)(g_y + (size_t)s0 * DIM);
    const __half2* y1p = (const __half2*)(g_y + (size_t)s1 * DIM);
    float2 ya = __half22float2(y0p[2 * t]);
    float2 yb = __half22float2(y0p[2 * t + 1]);
    float2 yc = __half22float2(y1p[2 * t]);
    float2 yd = __half22float2(y1p[2 * t + 1]);
    float4 v = make_float4(xv.x + ya.x + yc.x, xv.y + ya.y + yc.y,
                           xv.z + yb.x + yd.x, xv.w + yb.y + yd.y);
    float sum = v.x + v.y + v.z + v.w;
    float sq  = v.x * v.x + v.y * v.y + v.z * v.z + v.w * v.w;
    float2 r = block_reduce2(sum, sq);
    float mean = r.x * (1.f / DIM);
    float var  = r.y * (1.f / DIM) - mean * mean;
    float rstd = rsqrtf(var + EPS);

    float4 gg = ((const float4*)ln_g)[t];
    float4 bb = ((const float4*)ln_b)[t];
    float4 o = make_float4((v.x - mean) * rstd * gg.x + bb.x,
                           (v.y - mean) * rstd * gg.y + bb.y,
                           (v.z - mean) * rstd * gg.z + bb.z,
                           (v.w - mean) * rstd * gg.w + bb.w);
    ((float4*)(outp + (size_t)tkn * DIM))[t] = o;
}

// ---------------- launch ----------------
extern "C" void kernel_launch(void* const* d_in, const int* in_sizes, int n_in,
                              void* d_out, int out_size) {
    const float* x      = (const float*)d_in[0];
    const float* gate_w = (const float*)d_in[1];
    const float* w1     = (const float*)d_in[2];
    const float* b1     = (const float*)d_in[3];
    const float* ln1_g  = (const float*)d_in[4];
    const float* ln1_b  = (const float*)d_in[5];
    const float* w2     = (const float*)d_in[6];
    const float* b2     = (const float*)d_in[7];
    const float* ln_g   = (const float*)d_in[8];
    const float* ln_b   = (const float*)d_in[9];
    float* outp = (float*)d_out;

    cudaFuncSetAttribute(mma_gemm<HDIM, DIM, 0>,
                         cudaFuncAttributeMaxDynamicSharedMemorySize, MM_SMEM);
    cudaFuncSetAttribute(mma_gemm<DIM, HDIM, 1>,
                         cudaFuncAttributeMaxDynamicSharedMemorySize, MM_SMEM);

    // gate (+x->fp16) and w1 conversion, one launch (counters start at zero:
    // static init on first call, reset-by-combine on subsequent replays)
    gate_w1_kernel<<<GATE_CTA + WCONV_CTA, 256>>>(x, gate_w, w1);
    scatter_kernel<<<T / 256, 256>>>();

    // GEMM1: gathered x @ w1 + b1 -> g_act (fp16)
    mma_gemm<HDIM, DIM, 0><<<dim3(HDIM / 128, T / 128, E), NTHR, MM_SMEM>>>(b1);
    // LN1+GELU in-place and w2 conversion, one launch
    lngelu_w2_kernel<<<NSLOT + WCONV_CTA, 256>>>(ln1_g, ln1_b, w2);
    // GEMM2: act @ w2 + b2, gate-scaled -> g_y (fp16)
    mma_gemm<DIM, HDIM, 1><<<dim3(DIM / 128, T / 128, E), NTHR, MM_SMEM>>>(b2);
    combine_kernel<<<T, 256>>>(x, ln_g, ln_b, outp);
}